// round 4
// baseline (speedup 1.0000x reference)
#include <cuda_runtime.h>
#include <math.h>

#define Tt 96
#define Nn 1024
#define Gg 128
#define Hh 512
#define Ee 32768
#define ENe (Ee + Nn)
#define D2 56
#define INw 64
#define LSTM_CTAS 32

// ---------------- scratch (device globals: no runtime alloc allowed) ----------------
__device__ __align__(16) float g_XW[(size_t)Tt * Nn * Gg];   // XW1, then reused for XW2
__device__ __align__(16) float g_HB[(size_t)Tt * Nn * Gg];   // h1,  then reused for h2
__device__ float g_dinv[Tt * Nn];
__device__ float g_deg[Tt * Nn];
__device__ int   g_offs[Tt * (Nn + 1)];
__device__ int   g_cur[Tt * Nn];
__device__ int   g_srcbuf[(size_t)Tt * ENe];
__device__ float g_wbuf[(size_t)Tt * ENe];
__device__ float g_G2[Tt * D2];
__device__ float g_pre[Tt * 4 * Hh];
__device__ float g_hbuf[2 * Hh];
__device__ unsigned g_cnt;

// ---------------- zero init ----------------
__global__ void k_zero() {
    int i = blockIdx.x * blockDim.x + threadIdx.x;
    if (i < Tt * Nn) g_deg[i] = 0.f;
    if (i < Tt * D2) g_G2[i] = 0.f;
    if (i == 0) g_cnt = 0u;
}

// ---------------- degree histogram (incl. self loops); edge_index is INT32 ----------------
__global__ void k_deg(const int* __restrict__ ei) {
    int t = blockIdx.y;
    int i = blockIdx.x * blockDim.x + threadIdx.x;
    if (i >= ENe) return;
    int dst = (i < Ee) ? (ei[(size_t)t * 2 * Ee + Ee + i] & (Nn - 1)) : (i - Ee);
    atomicAdd(&g_deg[t * Nn + dst], 1.0f);
}

// ---------------- per-t scan -> CSR offsets, cursor, dinv ----------------
__global__ void k_scan() {
    int t = blockIdx.x, n = threadIdx.x;
    __shared__ int sc[Nn];
    int c = (int)g_deg[t * Nn + n];
    sc[n] = c;
    __syncthreads();
    for (int off = 1; off < Nn; off <<= 1) {
        int v = (n >= off) ? sc[n - off] : 0;
        __syncthreads();
        sc[n] += v;
        __syncthreads();
    }
    int ex = sc[n] - c;
    g_offs[t * (Nn + 1) + n] = ex;
    g_cur[t * Nn + n] = ex;
    if (n == Nn - 1) g_offs[t * (Nn + 1) + Nn] = sc[n];
    g_dinv[t * Nn + n] = rsqrtf((float)c);   // deg >= 1 always (self loop)
}

// ---------------- CSR fill (src and norm weight, grouped by dst); INT32 edges ----------------
__global__ void k_fill(const int* __restrict__ ei) {
    int t = blockIdx.y;
    int i = blockIdx.x * blockDim.x + threadIdx.x;
    if (i >= ENe) return;
    int s, d;
    if (i < Ee) {
        s = ei[(size_t)t * 2 * Ee + i] & (Nn - 1);
        d = ei[(size_t)t * 2 * Ee + Ee + i] & (Nn - 1);
    } else {
        s = d = i - Ee;
    }
    float w = g_dinv[t * Nn + s] * g_dinv[t * Nn + d];
    int pos = atomicAdd(&g_cur[t * Nn + d], 1);
    g_srcbuf[(size_t)t * ENe + pos] = s;
    g_wbuf[(size_t)t * ENe + pos] = w;
}

// ---------------- batched SGEMM: g_XW[t] (1024 x 128) = A[t] (1024 x K) @ B (K x 128) ----------------
template <int KK, bool EXT>
__global__ void __launch_bounds__(256) k_gemm(const float* __restrict__ Aext,
                                              const float* __restrict__ B) {
    const long long Astr = EXT ? (long long)Nn * Nn : (long long)Nn * Gg;
    const float* Abase = EXT ? Aext : (const float*)g_HB;
    int t = blockIdx.y;
    const float* At = Abase + (size_t)t * Astr + (size_t)blockIdx.x * 128 * KK;
    float* Ct = g_XW + (size_t)t * Nn * Gg + (size_t)blockIdx.x * 128 * Gg;
    __shared__ float As[16][132];
    __shared__ float Bs[16][128];
    int tid = threadIdx.x;
    int ty = tid >> 4, tx = tid & 15;
    float acc[8][8];
#pragma unroll
    for (int i = 0; i < 8; i++)
#pragma unroll
        for (int j = 0; j < 8; j++) acc[i][j] = 0.f;

    for (int k0 = 0; k0 < KK; k0 += 16) {
#pragma unroll
        for (int l = 0; l < 2; l++) {
            int idx = tid + l * 256;
            int m = idx >> 2, kk = (idx & 3) * 4;
            float4 va = *(const float4*)(At + (size_t)m * KK + k0 + kk);
            As[kk + 0][m] = va.x; As[kk + 1][m] = va.y;
            As[kk + 2][m] = va.z; As[kk + 3][m] = va.w;
            int r = idx >> 5, cc = (idx & 31) * 4;
            *(float4*)&Bs[r][cc] = *(const float4*)(B + (size_t)(k0 + r) * Gg + cc);
        }
        __syncthreads();
#pragma unroll
        for (int kk = 0; kk < 16; kk++) {
            float a[8], b[8];
#pragma unroll
            for (int i = 0; i < 8; i++) a[i] = As[kk][ty * 8 + i];
#pragma unroll
            for (int j = 0; j < 8; j++) b[j] = Bs[kk][tx * 8 + j];
#pragma unroll
            for (int i = 0; i < 8; i++)
#pragma unroll
                for (int j = 0; j < 8; j++) acc[i][j] += a[i] * b[j];
        }
        __syncthreads();
    }
#pragma unroll
    for (int i = 0; i < 8; i++) {
#pragma unroll
        for (int j4 = 0; j4 < 2; j4++) {
            float4 v = make_float4(acc[i][j4 * 4], acc[i][j4 * 4 + 1],
                                   acc[i][j4 * 4 + 2], acc[i][j4 * 4 + 3]);
            *(float4*)(Ct + (size_t)(ty * 8 + i) * Gg + tx * 8 + j4 * 4) = v;
        }
    }
}

// ---------------- SpMM: g_HB[t] = (relu?) (Ahat @ g_XW[t] + bias), gather by dst ----------------
template <bool RELU>
__global__ void k_spmm(const float* __restrict__ bias) {
    int t = blockIdx.y;
    int f = threadIdx.x;          // 128 = feature
    int n0 = blockIdx.x * 4;
    for (int nn = 0; nn < 4; nn++) {
        int n = n0 + nn;
        int beg = g_offs[t * (Nn + 1) + n], end = g_offs[t * (Nn + 1) + n + 1];
        float acc = bias[f];
        for (int e = beg; e < end; e++) {
            int s = g_srcbuf[(size_t)t * ENe + e];
            float w = g_wbuf[(size_t)t * ENe + e];
            acc += w * g_XW[((size_t)t * Nn + s) * Gg + f];
        }
        if (RELU) acc = fmaxf(acc, 0.f);
        g_HB[((size_t)t * Nn + n) * Gg + f] = acc;
    }
}

// ---------------- FC: G2[t][d] += this node's contribution, Wfc slice in smem ----------------
__global__ void k_fc(const float* __restrict__ Wfc) {
    int n = blockIdx.x;           // 1024 CTAs, one per node
    int tid = threadIdx.x;        // 128
    __shared__ float Wsm[Gg * D2];
    __shared__ float hs[Gg];
    for (int i = tid; i < Gg * D2; i += 128)
        Wsm[i] = Wfc[(size_t)n * Gg * D2 + i];
    __syncthreads();
    for (int t = 0; t < Tt; t++) {
        hs[tid] = g_HB[((size_t)t * Nn + n) * Gg + tid];
        __syncthreads();
        if (tid < D2) {
            float acc = 0.f;
#pragma unroll 8
            for (int k = 0; k < Gg; k++) acc += hs[k] * Wsm[k * D2 + tid];
            atomicAdd(&g_G2[t * D2 + tid], acc);
        }
        __syncthreads();
    }
}

// ---------------- LSTM pre-activations (everything except h @ W_h) ----------------
__global__ void k_pre(const float* __restrict__ x, const float* __restrict__ bfc,
                      const float* __restrict__ Wi0, const float* __restrict__ Wi1,
                      const float* __restrict__ Wi2, const float* __restrict__ Wi3,
                      const float* __restrict__ Wg0, const float* __restrict__ Wg1,
                      const float* __restrict__ Wg2, const float* __restrict__ Wg3,
                      const float* __restrict__ b0, const float* __restrict__ b1,
                      const float* __restrict__ b2, const float* __restrict__ b3) {
    int gid = blockIdx.x * blockDim.x + threadIdx.x;
    if (gid >= Tt * 4 * Hh) return;
    int j = gid & (Hh - 1);
    int gate = (gid >> 9) & 3;
    int t = gid >> 11;
    const float* Wi = gate == 0 ? Wi0 : gate == 1 ? Wi1 : gate == 2 ? Wi2 : Wi3;
    const float* Wg = gate == 0 ? Wg0 : gate == 1 ? Wg1 : gate == 2 ? Wg2 : Wg3;
    const float* bb = gate == 0 ? b0 : gate == 1 ? b1 : gate == 2 ? b2 : b3;
    float acc = bb[j];
#pragma unroll 8
    for (int k = 0; k < INw; k++) acc += x[t * INw + k] * Wi[k * Hh + j];
    for (int d = 0; d < D2; d++) {
        float gv = g_G2[t * D2 + d] + bfc[d];
        gv = gv > 0.f ? gv : 0.f;
        acc += gv * Wg[d * Hh + j];
    }
    g_pre[gid] = acc;
}

// ---------------- persistent recurrent LSTM: 32 CTAs, grid spin barrier per step ----------------
__global__ void __launch_bounds__(512, 1) k_lstm(const float* __restrict__ Whi,
                                                 const float* __restrict__ Whf,
                                                 const float* __restrict__ Whg,
                                                 const float* __restrict__ Who,
                                                 float* __restrict__ out, int out_size) {
    int tid = threadIdx.x, warp = tid >> 5, lane = tid & 31;
    int unit = blockIdx.x * 16 + warp;       // h-unit owned by this warp
    int gate = lane >> 3, q = lane & 7;      // 4 gates x 8 K-slices per warp
    const float* Wh = gate == 0 ? Whi : gate == 1 ? Whf : gate == 2 ? Whg : Who;

    // W_h slice in registers: k = (q + 8*mm)*4 + r
    float w[64];
#pragma unroll
    for (int mm = 0; mm < 16; mm++)
#pragma unroll
        for (int r = 0; r < 4; r++)
            w[mm * 4 + r] = Wh[(size_t)((q + 8 * mm) * 4 + r) * Hh + unit];

    __shared__ float sh[Hh];
    sh[tid] = 0.f;                            // h_0 = 0
    __syncthreads();
    float c = 0.f;

    for (int s = 0; s < Tt; s++) {
        const float4* sh4 = (const float4*)sh;
        float acc = 0.f;
#pragma unroll
        for (int mm = 0; mm < 16; mm++) {
            float4 v = sh4[q + 8 * mm];       // conflict-free, 4-gate broadcast
            acc += w[mm * 4 + 0] * v.x + w[mm * 4 + 1] * v.y +
                   w[mm * 4 + 2] * v.z + w[mm * 4 + 3] * v.w;
        }
        acc += __shfl_xor_sync(0xffffffffu, acc, 4);
        acc += __shfl_xor_sync(0xffffffffu, acc, 2);
        acc += __shfl_xor_sync(0xffffffffu, acc, 1);
        acc += g_pre[(s * 4 + gate) * Hh + unit];
        float vi = __shfl_sync(0xffffffffu, acc, 0);
        float vf = __shfl_sync(0xffffffffu, acc, 8);
        float vg = __shfl_sync(0xffffffffu, acc, 16);
        float vo = __shfl_sync(0xffffffffu, acc, 24);
        vi = 1.f / (1.f + expf(-vi));
        vf = 1.f / (1.f + expf(-vf));
        vo = 1.f / (1.f + expf(-vo));
        vg = tanhf(vg);
        c = vf * c + vi * vg;
        float h = vo * tanhf(c);
        if (lane == 0) {
            g_hbuf[(s & 1) * Hh + unit] = h;
            if (s * Hh + unit < out_size) out[s * Hh + unit] = h;
            if (s == Tt - 1) {
                if (Tt * Hh + unit < out_size) out[Tt * Hh + unit] = h;            // final h
                if (Tt * Hh + Hh + unit < out_size) out[Tt * Hh + Hh + unit] = c;  // final c
            }
            __threadfence();
        }
        __syncthreads();
        if (tid == 0) {
            atomicAdd(&g_cnt, 1u);
            unsigned target = (unsigned)(s + 1) * LSTM_CTAS;
            while (*((volatile unsigned*)&g_cnt) < target) {}
            __threadfence();
        }
        __syncthreads();
        sh[tid] = *((volatile float*)&g_hbuf[(s & 1) * Hh + tid]);  // bypass stale L1
        __syncthreads();
    }
}

// ---------------- launch: kernel launches ONLY ----------------
extern "C" void kernel_launch(void* const* d_in, const int* in_sizes, int n_in,
                              void* d_out, int out_size) {
    const float* x_in = (const float*)d_in[0];
    const float* xn   = (const float*)d_in[1];
    const int*   ei   = (const int*)d_in[2];   // jax x64 disabled -> int32 edge_index
    const float* W1 = (const float*)d_in[3];  const float* b1 = (const float*)d_in[4];
    const float* W2 = (const float*)d_in[5];  const float* b2 = (const float*)d_in[6];
    const float* Wfc = (const float*)d_in[7]; const float* bfc = (const float*)d_in[8];
    const float* Wii = (const float*)d_in[9];  const float* Wgi = (const float*)d_in[10];
    const float* Whi = (const float*)d_in[11]; const float* bi  = (const float*)d_in[12];
    const float* Wif = (const float*)d_in[13]; const float* Wgf = (const float*)d_in[14];
    const float* Whf = (const float*)d_in[15]; const float* bf_ = (const float*)d_in[16];
    const float* Wig = (const float*)d_in[17]; const float* Wgg = (const float*)d_in[18];
    const float* Whg = (const float*)d_in[19]; const float* bg  = (const float*)d_in[20];
    const float* Wio = (const float*)d_in[21]; const float* Wgo = (const float*)d_in[22];
    const float* Who = (const float*)d_in[23]; const float* bo  = (const float*)d_in[24];
    float* out = (float*)d_out;

    k_zero<<<(Tt * Nn + 255) / 256, 256>>>();

    dim3 eb((ENe + 255) / 256, Tt);
    k_deg<<<eb, 256>>>(ei);
    k_scan<<<Tt, Nn>>>();
    k_fill<<<eb, 256>>>(ei);

    // layer 1: XW1 = x_nodes @ W1 ; h1 = relu(Ahat XW1 + b1)
    k_gemm<Nn, true><<<dim3(8, Tt), 256>>>(xn, W1);
    k_spmm<true><<<dim3(Nn / 4, Tt), Gg>>>(b1);
    // layer 2: XW2 = h1 @ W2 ; h2 = Ahat XW2 + b2
    k_gemm<Gg, false><<<dim3(8, Tt), 256>>>(nullptr, W2);
    k_spmm<false><<<dim3(Nn / 4, Tt), Gg>>>(b2);
    // FC + LSTM pre-activations
    k_fc<<<Nn, 128>>>(Wfc);
    k_pre<<<(Tt * 4 * Hh + 255) / 256, 256>>>(x_in, bfc,
                                              Wii, Wif, Wig, Wio,
                                              Wgi, Wgf, Wgg, Wgo,
                                              bi, bf_, bg, bo);
    // sequential recurrence
    k_lstm<<<LSTM_CTAS, 512>>>(Whi, Whf, Whg, Who, out, out_size);

    (void)in_sizes; (void)n_in;
}

// round 7
// speedup vs baseline: 1.0009x; 1.0009x over previous
#include <cuda_runtime.h>
#include <cuda_bf16.h>
#include <math.h>
#include <cstdint>

#define Tt 96
#define Nn 1024
#define Gg 128
#define Hh 512
#define Ee 32768
#define ENe (Ee + Nn)
#define D2 56
#define INw 64
#define LSTM_CTAS 32

// ---------------- scratch (device globals: no runtime alloc allowed) ----------------
__device__ __align__(16) float g_XW[(size_t)Tt * Nn * Gg];   // XW1, then reused for XW2
__device__ __align__(16) float g_HB[(size_t)Tt * Nn * Gg];   // h1,  then reused for h2
__device__ float g_dinv[Tt * Nn];
__device__ float g_deg[Tt * Nn];
__device__ int   g_offs[Tt * (Nn + 1)];
__device__ int   g_cur[Tt * Nn];
__device__ int   g_srcbuf[(size_t)Tt * ENe];
__device__ float g_wbuf[(size_t)Tt * ENe];
__device__ float g_G2[Tt * D2];
__device__ float g_pre[Tt * 4 * Hh];
__device__ float g_hbuf[2 * Hh];
__device__ unsigned g_cnt;

// ---------------- zero init ----------------
__global__ void k_zero() {
    int i = blockIdx.x * blockDim.x + threadIdx.x;
    if (i < Tt * Nn) g_deg[i] = 0.f;
    if (i < Tt * D2) g_G2[i] = 0.f;
    if (i == 0) g_cnt = 0u;
}

// ---------------- degree histogram (incl. self loops); edge_index is INT32 ----------------
__global__ void k_deg(const int* __restrict__ ei) {
    int t = blockIdx.y;
    int i = blockIdx.x * blockDim.x + threadIdx.x;
    if (i >= ENe) return;
    int dst = (i < Ee) ? (ei[(size_t)t * 2 * Ee + Ee + i] & (Nn - 1)) : (i - Ee);
    atomicAdd(&g_deg[t * Nn + dst], 1.0f);
}

// ---------------- per-t scan -> CSR offsets, cursor, dinv ----------------
__global__ void k_scan() {
    int t = blockIdx.x, n = threadIdx.x;
    __shared__ int sc[Nn];
    int c = (int)g_deg[t * Nn + n];
    sc[n] = c;
    __syncthreads();
    for (int off = 1; off < Nn; off <<= 1) {
        int v = (n >= off) ? sc[n - off] : 0;
        __syncthreads();
        sc[n] += v;
        __syncthreads();
    }
    int ex = sc[n] - c;
    g_offs[t * (Nn + 1) + n] = ex;
    g_cur[t * Nn + n] = ex;
    if (n == Nn - 1) g_offs[t * (Nn + 1) + Nn] = sc[n];
    g_dinv[t * Nn + n] = rsqrtf((float)c);   // deg >= 1 always (self loop)
}

// ---------------- CSR fill (src and norm weight, grouped by dst); INT32 edges ----------------
__global__ void k_fill(const int* __restrict__ ei) {
    int t = blockIdx.y;
    int i = blockIdx.x * blockDim.x + threadIdx.x;
    if (i >= ENe) return;
    int s, d;
    if (i < Ee) {
        s = ei[(size_t)t * 2 * Ee + i] & (Nn - 1);
        d = ei[(size_t)t * 2 * Ee + Ee + i] & (Nn - 1);
    } else {
        s = d = i - Ee;
    }
    float w = g_dinv[t * Nn + s] * g_dinv[t * Nn + d];
    int pos = atomicAdd(&g_cur[t * Nn + d], 1);
    g_srcbuf[(size_t)t * ENe + pos] = s;
    g_wbuf[(size_t)t * ENe + pos] = w;
}

// ---------------- mma.sync helpers ----------------
__device__ __forceinline__ void mma16816(float* c, const uint32_t* a, uint32_t b0, uint32_t b1) {
    asm volatile(
        "mma.sync.aligned.m16n8k16.row.col.f32.bf16.bf16.f32 "
        "{%0,%1,%2,%3}, {%4,%5,%6,%7}, {%8,%9}, {%0,%1,%2,%3};"
        : "+f"(c[0]), "+f"(c[1]), "+f"(c[2]), "+f"(c[3])
        : "r"(a[0]), "r"(a[1]), "r"(a[2]), "r"(a[3]), "r"(b0), "r"(b1));
}
__device__ __forceinline__ uint32_t packbf2(float x, float y) {
    __nv_bfloat162 h = __floats2bfloat162_rn(x, y);
    return *(uint32_t*)&h;
}

// ---------------- tensor-core batched GEMM: g_XW[t] = A[t](1024 x KK) @ B(KK x 128) ----------------
// split-fp32 via bf16 hi/lo, 3 products (hi*hi + hi*lo + lo*hi) in fp32 accum.
// smem layout: [128 rows][36 words] per buffer (row stride 36 == 4 mod 32 -> conflict-free frags).
#define RS 36          // row stride in 32-bit words
template <int KK, bool EXT>
__global__ void __launch_bounds__(256) k_gemm_mma(const float* __restrict__ Aext,
                                                  const float* __restrict__ B) {
    extern __shared__ uint32_t sm[];
    uint32_t* smAh = sm;                 // 128*RS
    uint32_t* smAl = sm + 128 * RS;
    uint32_t* smBh = sm + 2 * 128 * RS;
    uint32_t* smBl = sm + 3 * 128 * RS;

    const int tid = threadIdx.x;
    const int wid = tid >> 5, lane = tid & 31;
    const int warp_m = wid & 3, warp_n = wid >> 2;   // 4 x 2 warps
    const int t = blockIdx.y;
    const size_t Astr = EXT ? (size_t)Nn * Nn : (size_t)Nn * Gg;
    const float* At = (EXT ? Aext : (const float*)g_HB) + (size_t)t * Astr + (size_t)blockIdx.x * 128 * KK;
    float* Ct = g_XW + ((size_t)t * Nn + (size_t)blockIdx.x * 128) * Gg;

    float acc[2][8][4];
#pragma unroll
    for (int mf = 0; mf < 2; mf++)
#pragma unroll
        for (int nf = 0; nf < 8; nf++)
#pragma unroll
            for (int r = 0; r < 4; r++) acc[mf][nf][r] = 0.f;

    const int lr = lane >> 2;       // 0..7
    const int lk = lane & 3;        // 0..3

    for (int k0 = 0; k0 < KK; k0 += 64) {
        // ---- stage A chunk: 128 x 64 fp32 -> bf16 hi/lo ----
        for (int i = tid; i < 2048; i += 256) {
            int r = i >> 4, q = i & 15;                 // row, float4 index (4 k's)
            float4 v = *(const float4*)(At + (size_t)r * KK + k0 + q * 4);
            float hx = __bfloat162float(__float2bfloat16_rn(v.x));
            float hy = __bfloat162float(__float2bfloat16_rn(v.y));
            float hz = __bfloat162float(__float2bfloat16_rn(v.z));
            float hw = __bfloat162float(__float2bfloat16_rn(v.w));
            int idx = r * RS + q * 2;
            smAh[idx]     = packbf2(v.x, v.y);
            smAh[idx + 1] = packbf2(v.z, v.w);
            smAl[idx]     = packbf2(v.x - hx, v.y - hy);
            smAl[idx + 1] = packbf2(v.z - hz, v.w - hw);
        }
        // ---- stage B chunk transposed: Bsm[n][k] = B[k0+k][n], bf16 hi/lo ----
        for (int i = tid; i < 2048; i += 256) {
            int k = i >> 5, q = i & 31;                 // k row, float4 over n
            float4 v = *(const float4*)(B + (size_t)(k0 + k) * Gg + q * 4);
            const float* vv = &v.x;
#pragma unroll
            for (int j = 0; j < 4; j++) {
                int n = q * 4 + j;
                float val = vv[j];
                __nv_bfloat16 hb = __float2bfloat16_rn(val);
                __nv_bfloat16 lb = __float2bfloat16_rn(val - __bfloat162float(hb));
                int hw_idx = (n * RS + (k >> 1)) * 2 + (k & 1);
                ((uint16_t*)smBh)[hw_idx] = *(uint16_t*)&hb;
                ((uint16_t*)smBl)[hw_idx] = *(uint16_t*)&lb;
            }
        }
        __syncthreads();

        // ---- compute: 4 k-steps of 16 ----
#pragma unroll
        for (int ks = 0; ks < 4; ks++) {
            uint32_t ah[2][4], al[2][4];
#pragma unroll
            for (int mf = 0; mf < 2; mf++) {
                int rm = warp_m * 32 + mf * 16 + lr;
                int kw = ks * 8 + lk;
                ah[mf][0] = smAh[rm * RS + kw];
                ah[mf][1] = smAh[(rm + 8) * RS + kw];
                ah[mf][2] = smAh[rm * RS + kw + 4];
                ah[mf][3] = smAh[(rm + 8) * RS + kw + 4];
                al[mf][0] = smAl[rm * RS + kw];
                al[mf][1] = smAl[(rm + 8) * RS + kw];
                al[mf][2] = smAl[rm * RS + kw + 4];
                al[mf][3] = smAl[(rm + 8) * RS + kw + 4];
            }
#pragma unroll
            for (int nf = 0; nf < 8; nf++) {
                int cn = warp_n * 64 + nf * 8 + lr;
                int kw = ks * 8 + lk;
                uint32_t bh0 = smBh[cn * RS + kw];
                uint32_t bh1 = smBh[cn * RS + kw + 4];
                uint32_t bl0 = smBl[cn * RS + kw];
                uint32_t bl1 = smBl[cn * RS + kw + 4];
#pragma unroll
                for (int mf = 0; mf < 2; mf++) {
                    mma16816(acc[mf][nf], ah[mf], bh0, bh1);
                    mma16816(acc[mf][nf], ah[mf], bl0, bl1);
                    mma16816(acc[mf][nf], al[mf], bh0, bh1);
                }
            }
        }
        __syncthreads();
    }

    // ---- epilogue ----
#pragma unroll
    for (int mf = 0; mf < 2; mf++) {
        int row = warp_m * 32 + mf * 16 + lr;
#pragma unroll
        for (int nf = 0; nf < 8; nf++) {
            int col = warp_n * 64 + nf * 8 + lk * 2;
            float* base = Ct + (size_t)row * Gg + col;
            *(float2*)base = make_float2(acc[mf][nf][0], acc[mf][nf][1]);
            *(float2*)(base + 8 * Gg) = make_float2(acc[mf][nf][2], acc[mf][nf][3]);
        }
    }
}

// ---------------- SpMM: g_HB[t] = (relu?) (Ahat @ g_XW[t] + bias), gather by dst ----------------
template <bool RELU>
__global__ void k_spmm(const float* __restrict__ bias) {
    int t = blockIdx.y;
    int f = threadIdx.x;          // 128 = feature
    int n0 = blockIdx.x * 4;
    for (int nn = 0; nn < 4; nn++) {
        int n = n0 + nn;
        int beg = g_offs[t * (Nn + 1) + n], end = g_offs[t * (Nn + 1) + n + 1];
        float acc = bias[f];
        for (int e = beg; e < end; e++) {
            int s = g_srcbuf[(size_t)t * ENe + e];
            float w = g_wbuf[(size_t)t * ENe + e];
            acc += w * g_XW[((size_t)t * Nn + s) * Gg + f];
        }
        if (RELU) acc = fmaxf(acc, 0.f);
        g_HB[((size_t)t * Nn + n) * Gg + f] = acc;
    }
}

// ---------------- FC: G2[t][d] += this node's contribution, Wfc slice in smem ----------------
__global__ void k_fc(const float* __restrict__ Wfc) {
    int n = blockIdx.x;           // 1024 CTAs, one per node
    int tid = threadIdx.x;        // 128
    __shared__ float Wsm[Gg * D2];
    __shared__ float hs[Gg];
    for (int i = tid; i < Gg * D2; i += 128)
        Wsm[i] = Wfc[(size_t)n * Gg * D2 + i];
    __syncthreads();
    for (int t = 0; t < Tt; t++) {
        hs[tid] = g_HB[((size_t)t * Nn + n) * Gg + tid];
        __syncthreads();
        if (tid < D2) {
            float acc = 0.f;
#pragma unroll 8
            for (int k = 0; k < Gg; k++) acc += hs[k] * Wsm[k * D2 + tid];
            atomicAdd(&g_G2[t * D2 + tid], acc);
        }
        __syncthreads();
    }
}

// ---------------- LSTM pre-activations (everything except h @ W_h) ----------------
__global__ void k_pre(const float* __restrict__ x, const float* __restrict__ bfc,
                      const float* __restrict__ Wi0, const float* __restrict__ Wi1,
                      const float* __restrict__ Wi2, const float* __restrict__ Wi3,
                      const float* __restrict__ Wg0, const float* __restrict__ Wg1,
                      const float* __restrict__ Wg2, const float* __restrict__ Wg3,
                      const float* __restrict__ b0, const float* __restrict__ b1,
                      const float* __restrict__ b2, const float* __restrict__ b3) {
    int gid = blockIdx.x * blockDim.x + threadIdx.x;
    if (gid >= Tt * 4 * Hh) return;
    int j = gid & (Hh - 1);
    int gate = (gid >> 9) & 3;
    int t = gid >> 11;
    const float* Wi = gate == 0 ? Wi0 : gate == 1 ? Wi1 : gate == 2 ? Wi2 : Wi3;
    const float* Wg = gate == 0 ? Wg0 : gate == 1 ? Wg1 : gate == 2 ? Wg2 : Wg3;
    const float* bb = gate == 0 ? b0 : gate == 1 ? b1 : gate == 2 ? b2 : b3;
    float acc = bb[j];
#pragma unroll 8
    for (int k = 0; k < INw; k++) acc += x[t * INw + k] * Wi[k * Hh + j];
    for (int d = 0; d < D2; d++) {
        float gv = g_G2[t * D2 + d] + bfc[d];
        gv = gv > 0.f ? gv : 0.f;
        acc += gv * Wg[d * Hh + j];
    }
    g_pre[gid] = acc;
}

// ---------------- persistent recurrent LSTM: 32 CTAs, grid spin barrier per step ----------------
__global__ void __launch_bounds__(512, 1) k_lstm(const float* __restrict__ Whi,
                                                 const float* __restrict__ Whf,
                                                 const float* __restrict__ Whg,
                                                 const float* __restrict__ Who,
                                                 float* __restrict__ out, int out_size) {
    int tid = threadIdx.x, warp = tid >> 5, lane = tid & 31;
    int unit = blockIdx.x * 16 + warp;       // h-unit owned by this warp
    int gate = lane >> 3, q = lane & 7;      // 4 gates x 8 K-slices per warp
    const float* Wh = gate == 0 ? Whi : gate == 1 ? Whf : gate == 2 ? Whg : Who;

    float w[64];
#pragma unroll
    for (int mm = 0; mm < 16; mm++)
#pragma unroll
        for (int r = 0; r < 4; r++)
            w[mm * 4 + r] = Wh[(size_t)((q + 8 * mm) * 4 + r) * Hh + unit];

    __shared__ float sh[Hh];
    sh[tid] = 0.f;
    __syncthreads();
    float c = 0.f;

    for (int s = 0; s < Tt; s++) {
        const float4* sh4 = (const float4*)sh;
        float acc = 0.f;
#pragma unroll
        for (int mm = 0; mm < 16; mm++) {
            float4 v = sh4[q + 8 * mm];
            acc += w[mm * 4 + 0] * v.x + w[mm * 4 + 1] * v.y +
                   w[mm * 4 + 2] * v.z + w[mm * 4 + 3] * v.w;
        }
        acc += __shfl_xor_sync(0xffffffffu, acc, 4);
        acc += __shfl_xor_sync(0xffffffffu, acc, 2);
        acc += __shfl_xor_sync(0xffffffffu, acc, 1);
        acc += g_pre[(s * 4 + gate) * Hh + unit];
        float vi = __shfl_sync(0xffffffffu, acc, 0);
        float vf = __shfl_sync(0xffffffffu, acc, 8);
        float vg = __shfl_sync(0xffffffffu, acc, 16);
        float vo = __shfl_sync(0xffffffffu, acc, 24);
        vi = 1.f / (1.f + expf(-vi));
        vf = 1.f / (1.f + expf(-vf));
        vo = 1.f / (1.f + expf(-vo));
        vg = tanhf(vg);
        c = vf * c + vi * vg;
        float h = vo * tanhf(c);
        if (lane == 0) {
            g_hbuf[(s & 1) * Hh + unit] = h;
            if (s * Hh + unit < out_size) out[s * Hh + unit] = h;
            if (s == Tt - 1) {
                if (Tt * Hh + unit < out_size) out[Tt * Hh + unit] = h;
                if (Tt * Hh + Hh + unit < out_size) out[Tt * Hh + Hh + unit] = c;
            }
            __threadfence();
        }
        __syncthreads();
        if (tid == 0) {
            atomicAdd(&g_cnt, 1u);
            unsigned target = (unsigned)(s + 1) * LSTM_CTAS;
            while (*((volatile unsigned*)&g_cnt) < target) {}
            __threadfence();
        }
        __syncthreads();
        sh[tid] = *((volatile float*)&g_hbuf[(s & 1) * Hh + tid]);
        __syncthreads();
    }
}

// ---------------- launch ----------------
extern "C" void kernel_launch(void* const* d_in, const int* in_sizes, int n_in,
                              void* d_out, int out_size) {
    const float* x_in = (const float*)d_in[0];
    const float* xn   = (const float*)d_in[1];
    const int*   ei   = (const int*)d_in[2];   // int32 edge_index (jax x64 disabled)
    const float* W1 = (const float*)d_in[3];  const float* b1 = (const float*)d_in[4];
    const float* W2 = (const float*)d_in[5];  const float* b2 = (const float*)d_in[6];
    const float* Wfc = (const float*)d_in[7]; const float* bfc = (const float*)d_in[8];
    const float* Wii = (const float*)d_in[9];  const float* Wgi = (const float*)d_in[10];
    const float* Whi = (const float*)d_in[11]; const float* bi  = (const float*)d_in[12];
    const float* Wif = (const float*)d_in[13]; const float* Wgf = (const float*)d_in[14];
    const float* Whf = (const float*)d_in[15]; const float* bf_ = (const float*)d_in[16];
    const float* Wig = (const float*)d_in[17]; const float* Wgg = (const float*)d_in[18];
    const float* Whg = (const float*)d_in[19]; const float* bg  = (const float*)d_in[20];
    const float* Wio = (const float*)d_in[21]; const float* Wgo = (const float*)d_in[22];
    const float* Who = (const float*)d_in[23]; const float* bo  = (const float*)d_in[24];
    float* out = (float*)d_out;

    const int GSM = 4 * 128 * RS * 4;   // 73728 B dynamic smem
    cudaFuncSetAttribute(k_gemm_mma<Nn, true>, cudaFuncAttributeMaxDynamicSharedMemorySize, GSM);
    cudaFuncSetAttribute(k_gemm_mma<Gg, false>, cudaFuncAttributeMaxDynamicSharedMemorySize, GSM);

    k_zero<<<(Tt * Nn + 255) / 256, 256>>>();

    dim3 eb((ENe + 255) / 256, Tt);
    k_deg<<<eb, 256>>>(ei);
    k_scan<<<Tt, Nn>>>();
    k_fill<<<eb, 256>>>(ei);

    // layer 1: XW1 = x_nodes @ W1 ; h1 = relu(Ahat XW1 + b1)
    k_gemm_mma<Nn, true><<<dim3(8, Tt), 256, GSM>>>(xn, W1);
    k_spmm<true><<<dim3(Nn / 4, Tt), Gg>>>(b1);
    // layer 2: XW2 = h1 @ W2 ; h2 = Ahat XW2 + b2
    k_gemm_mma<Gg, false><<<dim3(8, Tt), 256, GSM>>>(nullptr, W2);
    k_spmm<false><<<dim3(Nn / 4, Tt), Gg>>>(b2);
    // FC + LSTM pre-activations
    k_fc<<<Nn, 128>>>(Wfc);
    k_pre<<<(Tt * 4 * Hh + 255) / 256, 256>>>(x_in, bfc,
                                              Wii, Wif, Wig, Wio,
                                              Wgi, Wgf, Wgg, Wgo,
                                              bi, bf_, bg, bo);
    // sequential recurrence
    k_lstm<<<LSTM_CTAS, 512>>>(Whi, Whf, Whg, Who, out, out_size);

    (void)in_sizes; (void)n_in;
}

// round 10
// speedup vs baseline: 1.2896x; 1.2885x over previous
#include <cuda_runtime.h>
#include <cuda_bf16.h>
#include <math.h>
#include <cstdint>

#define Tt 96
#define Nn 1024
#define Gg 128
#define Hh 512
#define Ee 32768
#define ENe (Ee + Nn)
#define D2 56
#define INw 64
#define LSTM_CTAS 32
#define NREP 8

// ---------------- scratch ----------------
__device__ __align__(16) float g_XW[(size_t)Tt * Nn * Gg];
__device__ __align__(16) float g_HB[(size_t)Tt * Nn * Gg];
__device__ int   g_offs[Tt * (Nn + 1)];
__device__ __align__(8) int2 g_edge[(size_t)Tt * ENe];   // {src, w as float-bits}
__device__ float g_G2R[NREP * Tt * D2];
__device__ float g_G2[Tt * D2];
__device__ float g_pre[Tt * 4 * Hh];
__device__ float g_hbuf[2 * Hh];
__device__ unsigned g_cnt;

// ---------------- trivial zero kernels (also pad launch index for ncu) ----------------
__global__ void k_zero0() { if (threadIdx.x == 0 && blockIdx.x == 0) g_cnt = 0u; }
__global__ void k_zero1() {
    int i = blockIdx.x * blockDim.x + threadIdx.x;
    if (i < NREP * Tt * D2) g_G2R[i] = 0.f;
}

// ---------------- graph build: histogram + scan + CSR fill, one CTA per t ----------------
__global__ void __launch_bounds__(1024) k_build(const int* __restrict__ ei) {
    int t = blockIdx.x, tid = threadIdx.x;
    __shared__ int sc[Nn];
    __shared__ int cur[Nn];
    __shared__ float sdv[Nn];
    cur[tid] = 0;
    __syncthreads();
    for (int e = tid; e < Ee; e += 1024)
        atomicAdd(&cur[ei[(size_t)t * 2 * Ee + Ee + e] & (Nn - 1)], 1);
    __syncthreads();
    int c = cur[tid] + 1;                       // + self loop
    sdv[tid] = rsqrtf((float)c);
    sc[tid] = c;
    __syncthreads();
    for (int off = 1; off < Nn; off <<= 1) {
        int v = (tid >= off) ? sc[tid - off] : 0;
        __syncthreads();
        sc[tid] += v;
        __syncthreads();
    }
    int ex = sc[tid] - c;
    g_offs[t * (Nn + 1) + tid] = ex;
    if (tid == Nn - 1) g_offs[t * (Nn + 1) + Nn] = sc[tid];
    cur[tid] = ex;
    __syncthreads();
    for (int e = tid; e < ENe; e += 1024) {
        int s, d;
        if (e < Ee) {
            s = ei[(size_t)t * 2 * Ee + e] & (Nn - 1);
            d = ei[(size_t)t * 2 * Ee + Ee + e] & (Nn - 1);
        } else {
            s = d = e - Ee;
        }
        float w = sdv[s] * sdv[d];
        int pos = atomicAdd(&cur[d], 1);
        g_edge[(size_t)t * ENe + pos] = make_int2(s, __float_as_int(w));
    }
}

// ---------------- mma.sync helpers ----------------
__device__ __forceinline__ void mma16816(float* c, const uint32_t* a, uint32_t b0, uint32_t b1) {
    asm volatile(
        "mma.sync.aligned.m16n8k16.row.col.f32.bf16.bf16.f32 "
        "{%0,%1,%2,%3}, {%4,%5,%6,%7}, {%8,%9}, {%0,%1,%2,%3};"
        : "+f"(c[0]), "+f"(c[1]), "+f"(c[2]), "+f"(c[3])
        : "r"(a[0]), "r"(a[1]), "r"(a[2]), "r"(a[3]), "r"(b0), "r"(b1));
}
__device__ __forceinline__ uint32_t packbf2(float x, float y) {
    __nv_bfloat162 h = __floats2bfloat162_rn(x, y);
    return *(uint32_t*)&h;
}

// ---------------- tensor-core batched GEMM: g_XW[t] = A[t](1024 x KK) @ B(KK x 128) ----------------
#define RS 36
template <int KK, bool EXT>
__global__ void __launch_bounds__(256) k_gemm_mma(const float* __restrict__ Aext,
                                                  const float* __restrict__ B) {
    extern __shared__ uint32_t sm[];
    uint32_t* smAh = sm;
    uint32_t* smAl = sm + 128 * RS;
    uint32_t* smBh = sm + 2 * 128 * RS;
    uint32_t* smBl = sm + 3 * 128 * RS;

    const int tid = threadIdx.x;
    const int wid = tid >> 5, lane = tid & 31;
    const int warp_m = wid & 3, warp_n = wid >> 2;
    const int t = blockIdx.y;
    const size_t Astr = EXT ? (size_t)Nn * Nn : (size_t)Nn * Gg;
    const float* At = (EXT ? Aext : (const float*)g_HB) + (size_t)t * Astr + (size_t)blockIdx.x * 128 * KK;
    float* Ct = g_XW + ((size_t)t * Nn + (size_t)blockIdx.x * 128) * Gg;

    float acc[2][8][4];
#pragma unroll
    for (int mf = 0; mf < 2; mf++)
#pragma unroll
        for (int nf = 0; nf < 8; nf++)
#pragma unroll
            for (int r = 0; r < 4; r++) acc[mf][nf][r] = 0.f;

    const int lr = lane >> 2;
    const int lk = lane & 3;

    for (int k0 = 0; k0 < KK; k0 += 64) {
        // stage A: 128 x 64 fp32 -> bf16 hi/lo
        for (int i = tid; i < 2048; i += 256) {
            int r = i >> 4, q = i & 15;
            float4 v = *(const float4*)(At + (size_t)r * KK + k0 + q * 4);
            float hx = __bfloat162float(__float2bfloat16_rn(v.x));
            float hy = __bfloat162float(__float2bfloat16_rn(v.y));
            float hz = __bfloat162float(__float2bfloat16_rn(v.z));
            float hw = __bfloat162float(__float2bfloat16_rn(v.w));
            int idx = r * RS + q * 2;
            smAh[idx]     = packbf2(v.x, v.y);
            smAh[idx + 1] = packbf2(v.z, v.w);
            smAl[idx]     = packbf2(v.x - hx, v.y - hy);
            smAl[idx + 1] = packbf2(v.z - hz, v.w - hw);
        }
        // stage B transposed, paired-k 32-bit stores: word n*RS+k2 holds k=2k2,2k2+1
        for (int i = tid; i < 4096; i += 256) {
            int k2 = i >> 7, n = i & 127;
            float v0 = B[(size_t)(k0 + 2 * k2) * Gg + n];
            float v1 = B[(size_t)(k0 + 2 * k2 + 1) * Gg + n];
            float h0 = __bfloat162float(__float2bfloat16_rn(v0));
            float h1 = __bfloat162float(__float2bfloat16_rn(v1));
            smBh[n * RS + k2] = packbf2(v0, v1);
            smBl[n * RS + k2] = packbf2(v0 - h0, v1 - h1);
        }
        __syncthreads();

#pragma unroll
        for (int ks = 0; ks < 4; ks++) {
            uint32_t ah[2][4], al[2][4];
#pragma unroll
            for (int mf = 0; mf < 2; mf++) {
                int rm = warp_m * 32 + mf * 16 + lr;
                int kw = ks * 8 + lk;
                ah[mf][0] = smAh[rm * RS + kw];
                ah[mf][1] = smAh[(rm + 8) * RS + kw];
                ah[mf][2] = smAh[rm * RS + kw + 4];
                ah[mf][3] = smAh[(rm + 8) * RS + kw + 4];
                al[mf][0] = smAl[rm * RS + kw];
                al[mf][1] = smAl[(rm + 8) * RS + kw];
                al[mf][2] = smAl[rm * RS + kw + 4];
                al[mf][3] = smAl[(rm + 8) * RS + kw + 4];
            }
#pragma unroll
            for (int nf = 0; nf < 8; nf++) {
                int cn = warp_n * 64 + nf * 8 + lr;
                int kw = ks * 8 + lk;
                uint32_t bh0 = smBh[cn * RS + kw];
                uint32_t bh1 = smBh[cn * RS + kw + 4];
                uint32_t bl0 = smBl[cn * RS + kw];
                uint32_t bl1 = smBl[cn * RS + kw + 4];
#pragma unroll
                for (int mf = 0; mf < 2; mf++) {
                    mma16816(acc[mf][nf], ah[mf], bh0, bh1);
                    mma16816(acc[mf][nf], ah[mf], bl0, bl1);
                    mma16816(acc[mf][nf], al[mf], bh0, bh1);
                }
            }
        }
        __syncthreads();
    }

#pragma unroll
    for (int mf = 0; mf < 2; mf++) {
        int row = warp_m * 32 + mf * 16 + lr;
#pragma unroll
        for (int nf = 0; nf < 8; nf++) {
            int col = warp_n * 64 + nf * 8 + lk * 2;
            float* base = Ct + (size_t)row * Gg + col;
            *(float2*)base = make_float2(acc[mf][nf][0], acc[mf][nf][1]);
            *(float2*)(base + 8 * Gg) = make_float2(acc[mf][nf][2], acc[mf][nf][3]);
        }
    }
}

// ---------------- SpMM v2: warp per node, float4 per lane, shfl edge broadcast ----------------
template <bool RELU>
__global__ void __launch_bounds__(128) k_spmm(const float* __restrict__ bias) {
    int t = blockIdx.y;
    int warp = threadIdx.x >> 5, lane = threadIdx.x & 31;
    int n = blockIdx.x * 4 + warp;
    int beg = g_offs[t * (Nn + 1) + n], end = g_offs[t * (Nn + 1) + n + 1];
    const int2* ep = g_edge + (size_t)t * ENe;
    const float4* X4 = (const float4*)(g_XW + (size_t)t * Nn * Gg);
    float4 acc = *(const float4*)(bias + lane * 4);
    float4 a = make_float4(0.f, 0.f, 0.f, 0.f);

    int e = beg;
    for (; e + 32 <= end; e += 32) {
        int2 er = ep[e + lane];
#pragma unroll
        for (int j = 0; j < 32; j++) {
            int sj = __shfl_sync(0xffffffffu, er.x, j);
            float wj = __uint_as_float(__shfl_sync(0xffffffffu, er.y, j));
            float4 x = X4[(size_t)sj * 32 + lane];
            a.x += wj * x.x; a.y += wj * x.y; a.z += wj * x.z; a.w += wj * x.w;
        }
    }
    if (e < end) {
        int2 er = ep[min(e + lane, end - 1)];
        int cnt = end - e;
        for (int j = 0; j < cnt; j++) {
            int sj = __shfl_sync(0xffffffffu, er.x, j);
            float wj = __uint_as_float(__shfl_sync(0xffffffffu, er.y, j));
            float4 x = X4[(size_t)sj * 32 + lane];
            a.x += wj * x.x; a.y += wj * x.y; a.z += wj * x.z; a.w += wj * x.w;
        }
    }
    acc.x += a.x; acc.y += a.y; acc.z += a.z; acc.w += a.w;
    if (RELU) {
        acc.x = fmaxf(acc.x, 0.f); acc.y = fmaxf(acc.y, 0.f);
        acc.z = fmaxf(acc.z, 0.f); acc.w = fmaxf(acc.w, 0.f);
    }
    *(float4*)(g_HB + ((size_t)t * Nn + n) * Gg + lane * 4) = acc;
}

// ---------------- FC: per-node CTA, 4 timesteps per iteration, replicated accumulators ----------------
__global__ void __launch_bounds__(256) k_fc(const float* __restrict__ Wfc) {
    int n = blockIdx.x;
    int tid = threadIdx.x;
    __shared__ float Wsm[Gg * D2];
    __shared__ float hs[4][Gg];
    for (int i = tid; i < Gg * D2; i += 256)
        Wsm[i] = Wfc[(size_t)n * Gg * D2 + i];
    __syncthreads();
    int rep = n & (NREP - 1);
    for (int t0 = 0; t0 < Tt; t0 += 4) {
        for (int i = tid; i < 4 * Gg; i += 256)
            hs[i >> 7][i & 127] = g_HB[((size_t)(t0 + (i >> 7)) * Nn + n) * Gg + (i & 127)];
        __syncthreads();
        if (tid < 4 * D2) {
            int tt = tid / D2, d = tid % D2;
            float acc = 0.f;
#pragma unroll 8
            for (int k = 0; k < Gg; k++) acc += hs[tt][k] * Wsm[k * D2 + d];
            atomicAdd(&g_G2R[(rep * Tt + t0 + tt) * D2 + d], acc);
        }
        __syncthreads();
    }
}

// ---------------- sum replicas + bias + relu ----------------
__global__ void k_g2sum(const float* __restrict__ bfc) {
    int i = blockIdx.x * blockDim.x + threadIdx.x;
    if (i >= Tt * D2) return;
    int d = i % D2;
    float s = bfc[d];
#pragma unroll
    for (int r = 0; r < NREP; r++) s += g_G2R[r * Tt * D2 + i];
    g_G2[i] = fmaxf(s, 0.f);
}

// ---------------- LSTM pre-activations (everything except h @ W_h) ----------------
__global__ void k_pre(const float* __restrict__ x,
                      const float* __restrict__ Wi0, const float* __restrict__ Wi1,
                      const float* __restrict__ Wi2, const float* __restrict__ Wi3,
                      const float* __restrict__ Wg0, const float* __restrict__ Wg1,
                      const float* __restrict__ Wg2, const float* __restrict__ Wg3,
                      const float* __restrict__ b0, const float* __restrict__ b1,
                      const float* __restrict__ b2, const float* __restrict__ b3) {
    int gid = blockIdx.x * blockDim.x + threadIdx.x;
    if (gid >= Tt * 4 * Hh) return;
    int j = gid & (Hh - 1);
    int gate = (gid >> 9) & 3;
    int t = gid >> 11;
    const float* Wi = gate == 0 ? Wi0 : gate == 1 ? Wi1 : gate == 2 ? Wi2 : Wi3;
    const float* Wg = gate == 0 ? Wg0 : gate == 1 ? Wg1 : gate == 2 ? Wg2 : Wg3;
    const float* bb = gate == 0 ? b0 : gate == 1 ? b1 : gate == 2 ? b2 : b3;
    float acc = bb[j];
#pragma unroll 8
    for (int k = 0; k < INw; k++) acc += x[t * INw + k] * Wi[k * Hh + j];
#pragma unroll 8
    for (int d = 0; d < D2; d++) acc += g_G2[t * D2 + d] * Wg[d * Hh + j];
    g_pre[gid] = acc;
}

// ---------------- persistent recurrent LSTM ----------------
__global__ void __launch_bounds__(512, 1) k_lstm(const float* __restrict__ Whi,
                                                 const float* __restrict__ Whf,
                                                 const float* __restrict__ Whg,
                                                 const float* __restrict__ Who,
                                                 float* __restrict__ out, int out_size) {
    int tid = threadIdx.x, warp = tid >> 5, lane = tid & 31;
    int unit = blockIdx.x * 16 + warp;
    int gate = lane >> 3, q = lane & 7;
    const float* Wh = gate == 0 ? Whi : gate == 1 ? Whf : gate == 2 ? Whg : Who;

    float w[64];
#pragma unroll
    for (int mm = 0; mm < 16; mm++)
#pragma unroll
        for (int r = 0; r < 4; r++)
            w[mm * 4 + r] = Wh[(size_t)((q + 8 * mm) * 4 + r) * Hh + unit];

    __shared__ float sh[Hh];
    sh[tid] = 0.f;
    __syncthreads();
    float c = 0.f;

    for (int s = 0; s < Tt; s++) {
        const float4* sh4 = (const float4*)sh;
        float acc = 0.f;
#pragma unroll
        for (int mm = 0; mm < 16; mm++) {
            float4 v = sh4[q + 8 * mm];
            acc += w[mm * 4 + 0] * v.x + w[mm * 4 + 1] * v.y +
                   w[mm * 4 + 2] * v.z + w[mm * 4 + 3] * v.w;
        }
        acc += __shfl_xor_sync(0xffffffffu, acc, 4);
        acc += __shfl_xor_sync(0xffffffffu, acc, 2);
        acc += __shfl_xor_sync(0xffffffffu, acc, 1);
        acc += g_pre[(s * 4 + gate) * Hh + unit];
        float vi = __shfl_sync(0xffffffffu, acc, 0);
        float vf = __shfl_sync(0xffffffffu, acc, 8);
        float vg = __shfl_sync(0xffffffffu, acc, 16);
        float vo = __shfl_sync(0xffffffffu, acc, 24);
        vi = 1.f / (1.f + expf(-vi));
        vf = 1.f / (1.f + expf(-vf));
        vo = 1.f / (1.f + expf(-vo));
        vg = tanhf(vg);
        c = vf * c + vi * vg;
        float h = vo * tanhf(c);
        if (lane == 0) {
            g_hbuf[(s & 1) * Hh + unit] = h;
            if (s * Hh + unit < out_size) out[s * Hh + unit] = h;
            if (s == Tt - 1) {
                if (Tt * Hh + unit < out_size) out[Tt * Hh + unit] = h;
                if (Tt * Hh + Hh + unit < out_size) out[Tt * Hh + Hh + unit] = c;
            }
            __threadfence();
        }
        __syncthreads();
        if (tid == 0) {
            atomicAdd(&g_cnt, 1u);
            unsigned target = (unsigned)(s + 1) * LSTM_CTAS;
            while (*((volatile unsigned*)&g_cnt) < target) {}
            __threadfence();
        }
        __syncthreads();
        sh[tid] = *((volatile float*)&g_hbuf[(s & 1) * Hh + tid]);
        __syncthreads();
    }
}

// ---------------- launch ----------------
extern "C" void kernel_launch(void* const* d_in, const int* in_sizes, int n_in,
                              void* d_out, int out_size) {
    const float* x_in = (const float*)d_in[0];
    const float* xn   = (const float*)d_in[1];
    const int*   ei   = (const int*)d_in[2];
    const float* W1 = (const float*)d_in[3];  const float* b1 = (const float*)d_in[4];
    const float* W2 = (const float*)d_in[5];  const float* b2 = (const float*)d_in[6];
    const float* Wfc = (const float*)d_in[7]; const float* bfc = (const float*)d_in[8];
    const float* Wii = (const float*)d_in[9];  const float* Wgi = (const float*)d_in[10];
    const float* Whi = (const float*)d_in[11]; const float* bi  = (const float*)d_in[12];
    const float* Wif = (const float*)d_in[13]; const float* Wgf = (const float*)d_in[14];
    const float* Whf = (const float*)d_in[15]; const float* bf_ = (const float*)d_in[16];
    const float* Wig = (const float*)d_in[17]; const float* Wgg = (const float*)d_in[18];
    const float* Whg = (const float*)d_in[19]; const float* bg  = (const float*)d_in[20];
    const float* Wio = (const float*)d_in[21]; const float* Wgo = (const float*)d_in[22];
    const float* Who = (const float*)d_in[23]; const float* bo  = (const float*)d_in[24];
    float* out = (float*)d_out;

    const int GSM = 4 * 128 * RS * 4;
    cudaFuncSetAttribute(k_gemm_mma<Nn, true>, cudaFuncAttributeMaxDynamicSharedMemorySize, GSM);
    cudaFuncSetAttribute(k_gemm_mma<Gg, false>, cudaFuncAttributeMaxDynamicSharedMemorySize, GSM);

    k_zero0<<<1, 32>>>();                                        // launch 0
    k_zero1<<<(NREP * Tt * D2 + 255) / 256, 256>>>();            // launch 1
    k_build<<<Tt, 1024>>>(ei);                                   // launch 2
    k_gemm_mma<Nn, true><<<dim3(8, Tt), 256, GSM>>>(xn, W1);     // launch 3  <- profiled
    k_spmm<true><<<dim3(Nn / 4, Tt), 128>>>(b1);                 // launch 4
    k_gemm_mma<Gg, false><<<dim3(8, Tt), 256, GSM>>>(nullptr, W2); // 5
    k_spmm<false><<<dim3(Nn / 4, Tt), 128>>>(b2);                // 6
    k_fc<<<Nn, 256>>>(Wfc);                                      // 7
    k_g2sum<<<(Tt * D2 + 255) / 256, 256>>>(bfc);                // 8
    k_pre<<<(Tt * 4 * Hh + 255) / 256, 256>>>(x_in,
                                              Wii, Wif, Wig, Wio,
                                              Wgi, Wgf, Wgg, Wgo,
                                              bi, bf_, bg, bo);  // 9
    k_lstm<<<LSTM_CTAS, 512>>>(Whi, Whf, Whg, Who, out, out_size); // 10

    (void)in_sizes; (void)n_in;
}